// round 1
// baseline (speedup 1.0000x reference)
#include <cuda_runtime.h>

// Flow1: z = eps*exp(0.5*logvar)+mean, 4 affine-coupling half-layers, densities.
// B=262144 rows, Z=128, ZH=64, HS=50, NF=2 (-> 4 couplings).
// Output layout: [ z (B*128) | logpz (B) | logqz (B) ] fp32.

#define ZZ   128
#define ZH   64
#define HS   50
#define HSP  52      // HS padded to multiple of 4 for float4 shared loads
#define NC   4       // total coupling half-layers
#define TPB  256

// Shared-memory layout (floats); all offsets multiples of 4 floats (16B aligned)
#define SW0_OFF 0
#define SB0_OFF (NC*HS*ZH)               // 12800
#define SW1_OFF (SB0_OFF + NC*HS)        // 13000
#define SB1_OFF (SW1_OFF + NC*ZH*HSP)    // 26312
#define SW2_OFF (SB1_OFF + NC*ZH)        // 26568
#define SB2_OFF (SW2_OFF + NC*ZH*HSP)    // 39880
#define SMEM_FLOATS (SB2_OFF + NC*ZH)    // 40136
#define SMEM_BYTES  (SMEM_FLOATS * 4)    // 160544 B

// Accurate-enough fast tanh: tanh(x) = 1 - 2/(exp(2x)+1).
// __expf rel err ~1e-7; handles |x| large via inf/0 saturation.
__device__ __forceinline__ float fast_tanh(float x) {
    float e = __expf(2.0f * x);
    return 1.0f - 2.0f * __fdividef(1.0f, e + 1.0f);
}

// One coupling half-layer: reads a[], updates bz[] in place, returns logdet contribution.
__device__ __forceinline__ float coupling(
    const float (&a)[ZH], float (&bz)[ZH],
    const float* __restrict__ w0, const float* __restrict__ b0,
    const float* __restrict__ w1, const float* __restrict__ b1,
    const float* __restrict__ w2, const float* __restrict__ b2)
{
    float h[HSP];
#pragma unroll
    for (int j = 0; j < HS; j++) {
        float acc = b0[j];
        const float4* w = reinterpret_cast<const float4*>(w0 + j * ZH);
#pragma unroll
        for (int k = 0; k < ZH / 4; k++) {
            float4 wv = w[k];
            acc = fmaf(wv.x, a[4 * k + 0], acc);
            acc = fmaf(wv.y, a[4 * k + 1], acc);
            acc = fmaf(wv.z, a[4 * k + 2], acc);
            acc = fmaf(wv.w, a[4 * k + 3], acc);
        }
        h[j] = fast_tanh(acc);
    }
    h[HS] = 0.0f;
    h[HS + 1] = 0.0f;

    float logdet = 0.0f;
#pragma unroll
    for (int i = 0; i < ZH; i++) {
        float mu = b1[i];
        float sg = b2[i];
        const float4* r1 = reinterpret_cast<const float4*>(w1 + i * HSP);
        const float4* r2 = reinterpret_cast<const float4*>(w2 + i * HSP);
#pragma unroll
        for (int j = 0; j < HSP / 4; j++) {
            float4 v1 = r1[j];
            float4 v2 = r2[j];
            mu = fmaf(v1.x, h[4 * j + 0], mu);
            mu = fmaf(v1.y, h[4 * j + 1], mu);
            mu = fmaf(v1.z, h[4 * j + 2], mu);
            mu = fmaf(v1.w, h[4 * j + 3], mu);
            sg = fmaf(v2.x, h[4 * j + 0], sg);
            sg = fmaf(v2.y, h[4 * j + 1], sg);
            sg = fmaf(v2.z, h[4 * j + 2], sg);
            sg = fmaf(v2.w, h[4 * j + 3], sg);
        }
        // sigmoid + log(sigmoid) via one exp: sig = 1/(1+e^-x); log sig = -log(1+e^-x)
        float ex  = __expf(-sg);
        float sig = __fdividef(1.0f, 1.0f + ex);
        bz[i] = fmaf(bz[i], sig, mu);
        logdet -= __logf(1.0f + ex);
    }
    return logdet;
}

__global__ void __launch_bounds__(TPB, 1)
flow_kernel(const float* __restrict__ mean,  const float* __restrict__ logvar,
            const float* __restrict__ eps,
            const float* __restrict__ W_in,  const float* __restrict__ b_in,
            const float* __restrict__ W_mu,  const float* __restrict__ b_mu,
            const float* __restrict__ W_sig, const float* __restrict__ b_sig,
            float* __restrict__ out, int Brows)
{
    extern __shared__ float smem[];
    float* sW0 = smem + SW0_OFF;
    float* sb0 = smem + SB0_OFF;
    float* sW1 = smem + SW1_OFF;
    float* sb1 = smem + SB1_OFF;
    float* sW2 = smem + SW2_OFF;
    float* sb2 = smem + SB2_OFF;

    // Stage all coupling weights once per CTA.
    for (int idx = threadIdx.x; idx < NC * HS * ZH; idx += TPB) sW0[idx] = W_in[idx];
    for (int idx = threadIdx.x; idx < NC * HS;      idx += TPB) sb0[idx] = b_in[idx];
    for (int idx = threadIdx.x; idx < NC * ZH * HSP; idx += TPB) {
        int r = idx / HSP;
        int c = idx - r * HSP;
        float vm = 0.0f, vs = 0.0f;
        if (c < HS) { vm = W_mu[r * HS + c]; vs = W_sig[r * HS + c]; }
        sW1[idx] = vm;
        sW2[idx] = vs;
    }
    for (int idx = threadIdx.x; idx < NC * ZH; idx += TPB) {
        sb1[idx] = b_mu[idx];
        sb2[idx] = b_sig[idx];
    }
    __syncthreads();

    int row = blockIdx.x * TPB + threadIdx.x;
    if (row >= Brows) return;

    const float4* m4 = reinterpret_cast<const float4*>(mean   + (size_t)row * ZZ);
    const float4* l4 = reinterpret_cast<const float4*>(logvar + (size_t)row * ZZ);
    const float4* e4 = reinterpret_cast<const float4*>(eps    + (size_t)row * ZZ);

    float z1[ZH], z2[ZH];
    float slv = 0.0f, se2 = 0.0f;

    // z = eps*exp(0.5*logvar)+mean; logqz0 = -0.5*(sum logvar + sum eps^2)
    // ((z-mean)^2/exp(logvar) == eps^2 exactly in real arithmetic)
#define PE(mm, ll, ee, kk)                                        \
    do {                                                          \
        float s_ = __expf(0.5f * (ll));                           \
        float z_ = fmaf((ee), s_, (mm));                          \
        if ((kk) < ZH) z1[(kk)] = z_; else z2[(kk) - ZH] = z_;    \
        slv += (ll);                                              \
        se2 = fmaf((ee), (ee), se2);                              \
    } while (0)

#pragma unroll
    for (int q = 0; q < ZZ / 4; q++) {
        float4 mv = m4[q];
        float4 lv = l4[q];
        float4 ev = e4[q];
        PE(mv.x, lv.x, ev.x, 4 * q + 0);
        PE(mv.y, lv.y, ev.y, 4 * q + 1);
        PE(mv.z, lv.z, ev.z, 4 * q + 2);
        PE(mv.w, lv.w, ev.w, 4 * q + 3);
    }
#undef PE
    float logqz0 = -0.5f * (slv + se2);

    // Coupling sequence: c = i*2 + half; alternates (z1 -> update z2), (z2 -> update z1).
    float logdet = 0.0f;
    logdet += coupling(z1, z2, sW0 + 0 * HS * ZH, sb0 + 0 * HS,
                       sW1 + 0 * ZH * HSP, sb1 + 0 * ZH, sW2 + 0 * ZH * HSP, sb2 + 0 * ZH);
    logdet += coupling(z2, z1, sW0 + 1 * HS * ZH, sb0 + 1 * HS,
                       sW1 + 1 * ZH * HSP, sb1 + 1 * ZH, sW2 + 1 * ZH * HSP, sb2 + 1 * ZH);
    logdet += coupling(z1, z2, sW0 + 2 * HS * ZH, sb0 + 2 * HS,
                       sW1 + 2 * ZH * HSP, sb1 + 2 * ZH, sW2 + 2 * ZH * HSP, sb2 + 2 * ZH);
    logdet += coupling(z2, z1, sW0 + 3 * HS * ZH, sb0 + 3 * HS,
                       sW1 + 3 * ZH * HSP, sb1 + 3 * ZH, sW2 + 3 * ZH * HSP, sb2 + 3 * ZH);

    // Epilogue: write z = [z1 | z2], logpz = -0.5*sum z^2, logqz = logqz0 - logdet.
    float4* oz = reinterpret_cast<float4*>(out + (size_t)row * ZZ);
    float ss = 0.0f;
#pragma unroll
    for (int q = 0; q < ZH / 4; q++) {
        float4 v = make_float4(z1[4 * q + 0], z1[4 * q + 1], z1[4 * q + 2], z1[4 * q + 3]);
        ss = fmaf(v.x, v.x, ss);
        ss = fmaf(v.y, v.y, ss);
        ss = fmaf(v.z, v.z, ss);
        ss = fmaf(v.w, v.w, ss);
        oz[q] = v;
    }
#pragma unroll
    for (int q = 0; q < ZH / 4; q++) {
        float4 v = make_float4(z2[4 * q + 0], z2[4 * q + 1], z2[4 * q + 2], z2[4 * q + 3]);
        ss = fmaf(v.x, v.x, ss);
        ss = fmaf(v.y, v.y, ss);
        ss = fmaf(v.z, v.z, ss);
        ss = fmaf(v.w, v.w, ss);
        oz[ZH / 4 + q] = v;
    }

    size_t base = (size_t)Brows * ZZ;
    out[base + row]         = -0.5f * ss;
    out[base + Brows + row] = logqz0 - logdet;
}

extern "C" void kernel_launch(void* const* d_in, const int* in_sizes, int n_in,
                              void* d_out, int out_size)
{
    const float* mean   = (const float*)d_in[0];
    const float* logvar = (const float*)d_in[1];
    const float* eps    = (const float*)d_in[2];
    const float* W_in   = (const float*)d_in[3];
    const float* b_in   = (const float*)d_in[4];
    const float* W_mu   = (const float*)d_in[5];
    const float* b_mu   = (const float*)d_in[6];
    const float* W_sig  = (const float*)d_in[7];
    const float* b_sig  = (const float*)d_in[8];
    float* out = (float*)d_out;

    int Brows = in_sizes[0] / ZZ;

    cudaFuncSetAttribute(flow_kernel, cudaFuncAttributeMaxDynamicSharedMemorySize, SMEM_BYTES);

    int grid = (Brows + TPB - 1) / TPB;
    flow_kernel<<<grid, TPB, SMEM_BYTES>>>(mean, logvar, eps,
                                           W_in, b_in, W_mu, b_mu, W_sig, b_sig,
                                           out, Brows);
}

// round 2
// speedup vs baseline: 3.2750x; 3.2750x over previous
#include <cuda_runtime.h>

// Flow1: reparam + 4 affine-coupling half-layers + densities.
// B=262144 rows, Z=128, ZH=64, HS=50 (padded to 64), NF=2 -> 4 couplings.
// Output: [ z (B*128) | logpz (B) | logqz (B) ] fp32.
//
// CTA processes R=64 rows. All activations in SMEM, transposed [k][row] with
// pitch 68 floats. Each GEMM is 64x64x64; each thread owns a 4x4 output tile
// (16x16 thread grid), register-blocked with float4 LDS.

#define ZZ   128
#define ZH   64
#define HS   50
#define NC   4
#define TPB  256
#define RR   64        // rows per CTA
#define PIT  68        // transposed-tile pitch (floats), mult of 4

// shared layout (float offsets)
#define OFF_Z1   0
#define OFF_Z2   (OFF_Z1 + 64*PIT)      // 4352
#define OFF_H    (OFF_Z2 + 64*PIT)      // 8704
#define OFF_W0   (OFF_H  + 64*PIT)      // 13056
#define OFF_W1   (OFF_W0 + 64*PIT)      // 17408
#define OFF_W2   (OFF_W1 + 64*PIT)      // 21760
#define OFF_B0   (OFF_W2 + 64*PIT)      // 26112
#define OFF_B1   (OFF_B0 + 64)
#define OFF_B2   (OFF_B1 + 64)
#define OFF_Q0   (OFF_B2 + 64)
#define SMEM_FLOATS (OFF_Q0 + 64)       // 26368
#define SMEM_BYTES  (SMEM_FLOATS * 4)   // 105472
// reduction scratch aliases OFF_H after last coupling:
#define OFF_SS   OFF_H                   // 16*64 floats
#define OFF_LD   (OFF_H + 1024)          // 16*64 floats

__device__ __forceinline__ float tanh_fast(float x) {
    float r;
    asm("tanh.approx.f32 %0, %1;" : "=f"(r) : "f"(x));
    return r;
}

__global__ void __launch_bounds__(TPB, 2)
flow_kernel(const float* __restrict__ mean,  const float* __restrict__ logvar,
            const float* __restrict__ eps,
            const float* __restrict__ W_in,  const float* __restrict__ b_in,
            const float* __restrict__ W_mu,  const float* __restrict__ b_mu,
            const float* __restrict__ W_sig, const float* __restrict__ b_sig,
            float* __restrict__ out, int Brows)
{
    extern __shared__ float sm[];
    float* sZ1 = sm + OFF_Z1;
    float* sZ2 = sm + OFF_Z2;
    float* sH  = sm + OFF_H;
    float* sW0 = sm + OFF_W0;
    float* sW1 = sm + OFF_W1;
    float* sW2 = sm + OFF_W2;
    float* sB0 = sm + OFF_B0;
    float* sB1 = sm + OFF_B1;
    float* sB2 = sm + OFF_B2;
    float* sQ0 = sm + OFF_Q0;

    const int tid = threadIdx.x;
    const int wl  = tid & 31;          // lane
    const int wd  = tid >> 5;          // warp
    const int tr  = tid & 15;          // tile row group
    const int tc  = tid >> 4;          // tile col group
    const int r0  = tr * 4;
    const int c0  = tc * 4;
    const int rowBase = blockIdx.x * RR;

    // ---------------- reparam load phase ----------------
    // thread t handles quads f = t + 256*i : row = wd + 8*i, quad = wl (k = 4*wl)
#pragma unroll
    for (int i = 0; i < 8; i++) {
        int row  = wd + 8 * i;
        int gRow = rowBase + row;
        const float4 mv = reinterpret_cast<const float4*>(mean  )[(size_t)gRow * 32 + wl];
        const float4 lv = reinterpret_cast<const float4*>(logvar)[(size_t)gRow * 32 + wl];
        const float4 ev = reinterpret_cast<const float4*>(eps   )[(size_t)gRow * 32 + wl];
        float z[4];
        z[0] = fmaf(ev.x, __expf(0.5f * lv.x), mv.x);
        z[1] = fmaf(ev.y, __expf(0.5f * lv.y), mv.y);
        z[2] = fmaf(ev.z, __expf(0.5f * lv.z), mv.z);
        z[3] = fmaf(ev.w, __expf(0.5f * lv.w), mv.w);
        float part = lv.x + lv.y + lv.z + lv.w;
        part = fmaf(ev.x, ev.x, part);
        part = fmaf(ev.y, ev.y, part);
        part = fmaf(ev.z, ev.z, part);
        part = fmaf(ev.w, ev.w, part);
        int k = 4 * wl;
        if (k < ZH) {
#pragma unroll
            for (int d = 0; d < 4; d++) sZ1[(k + d) * PIT + row] = z[d];
        } else {
#pragma unroll
            for (int d = 0; d < 4; d++) sZ2[(k - ZH + d) * PIT + row] = z[d];
        }
        // per-row reduction: all 32 lanes of this warp share `row`
#pragma unroll
        for (int s = 16; s > 0; s >>= 1)
            part += __shfl_xor_sync(0xffffffffu, part, s);
        if (wl == 0) sQ0[row] = -0.5f * part;
    }
    __syncthreads();

    float ld_part[4] = {0.f, 0.f, 0.f, 0.f};   // sum log(sig) for my 4 rows
    float ss_part[4] = {0.f, 0.f, 0.f, 0.f};   // sum z^2 (final) for my 4 rows

    // ---------------- couplings ----------------
#pragma unroll 1
    for (int c = 0; c < NC; c++) {
        // ---- stage this coupling's weights (transposed, zero-padded) ----
        // W0: raw [HS][ZH] -> sW0[k*PIT + j], rows j>=HS zero
        for (int idx = tid; idx < 64 * 64; idx += TPB) {
            int j = idx >> 6, k = idx & 63;
            float v = (idx < HS * ZH) ? W_in[c * HS * ZH + idx] : 0.0f;
            sW0[k * PIT + j] = v;
        }
        // W1/W2: raw [ZH][HS] -> sW[j*PIT + i], rows j>=HS zero
        for (int idx = tid; idx < ZH * HS; idx += TPB) {
            int io = idx / HS, j = idx - io * HS;
            sW1[j * PIT + io] = W_mu [c * ZH * HS + idx];
            sW2[j * PIT + io] = W_sig[c * ZH * HS + idx];
        }
        for (int idx = tid; idx < (64 - HS) * 64; idx += TPB) {
            int j = HS + (idx >> 6), i = idx & 63;
            sW1[j * PIT + i] = 0.0f;
            sW2[j * PIT + i] = 0.0f;
        }
        if (tid < 64) {
            sB0[tid] = (tid < HS) ? b_in[c * HS + tid] : 0.0f;
            sB1[tid] = b_mu [c * ZH + tid];
            sB2[tid] = b_sig[c * ZH + tid];
        }
        __syncthreads();

        const float* sZa = (c & 1) ? sZ2 : sZ1;   // coupling input
        float*       sZu = (c & 1) ? sZ1 : sZ2;   // coupling target

        // ---- GEMM1: H = tanh(Za @ W0^T + b0), 64x64x64 ----
        {
            float acc[4][4] = {};
#pragma unroll 8
            for (int k = 0; k < 64; k++) {
                float4 a = *reinterpret_cast<const float4*>(&sZa[k * PIT + r0]);
                float4 b = *reinterpret_cast<const float4*>(&sW0[k * PIT + c0]);
                const float av[4] = {a.x, a.y, a.z, a.w};
                const float bv[4] = {b.x, b.y, b.z, b.w};
#pragma unroll
                for (int i = 0; i < 4; i++)
#pragma unroll
                    for (int j = 0; j < 4; j++)
                        acc[i][j] = fmaf(av[i], bv[j], acc[i][j]);
            }
#pragma unroll
            for (int j = 0; j < 4; j++) {
                float bb = sB0[c0 + j];
#pragma unroll
                for (int i = 0; i < 4; i++)
                    sH[(c0 + j) * PIT + (r0 + i)] = tanh_fast(acc[i][j] + bb);
            }
        }
        __syncthreads();

        // ---- GEMM2: mu/sig heads + z update + logdet ----
        {
            float am[4][4] = {};
            float as[4][4] = {};
#pragma unroll 4
            for (int k = 0; k < 64; k++) {
                float4 a  = *reinterpret_cast<const float4*>(&sH [k * PIT + r0]);
                float4 b1 = *reinterpret_cast<const float4*>(&sW1[k * PIT + c0]);
                float4 b2 = *reinterpret_cast<const float4*>(&sW2[k * PIT + c0]);
                const float av[4]  = {a.x, a.y, a.z, a.w};
                const float b1v[4] = {b1.x, b1.y, b1.z, b1.w};
                const float b2v[4] = {b2.x, b2.y, b2.z, b2.w};
#pragma unroll
                for (int i = 0; i < 4; i++)
#pragma unroll
                    for (int j = 0; j < 4; j++) {
                        am[i][j] = fmaf(av[i], b1v[j], am[i][j]);
                        as[i][j] = fmaf(av[i], b2v[j], as[i][j]);
                    }
            }
            bool takeSS = (c >= 2);   // c==2: z2 final, c==3: z1 final
#pragma unroll
            for (int j = 0; j < 4; j++) {
                float bm = sB1[c0 + j];
                float bs = sB2[c0 + j];
#pragma unroll
                for (int i = 0; i < 4; i++) {
                    float m  = am[i][j] + bm;
                    float sg = as[i][j] + bs;
                    float ex  = __expf(-sg);
                    float sig = __fdividef(1.0f, 1.0f + ex);
                    float zo = sZu[(c0 + j) * PIT + (r0 + i)];
                    float zn = fmaf(zo, sig, m);
                    sZu[(c0 + j) * PIT + (r0 + i)] = zn;
                    ld_part[i] -= __logf(1.0f + ex);           // += log(sig)
                    if (takeSS) ss_part[i] = fmaf(zn, zn, ss_part[i]);
                }
            }
        }
        __syncthreads();
    }

    // ---------------- write z ----------------
#pragma unroll
    for (int i = 0; i < 8; i++) {
        int row  = wd + 8 * i;
        int gRow = rowBase + row;
        int k = 4 * wl;
        float4 v;
        if (k < ZH) {
            v.x = sZ1[(k + 0) * PIT + row];
            v.y = sZ1[(k + 1) * PIT + row];
            v.z = sZ1[(k + 2) * PIT + row];
            v.w = sZ1[(k + 3) * PIT + row];
        } else {
            v.x = sZ2[(k - ZH + 0) * PIT + row];
            v.y = sZ2[(k - ZH + 1) * PIT + row];
            v.z = sZ2[(k - ZH + 2) * PIT + row];
            v.w = sZ2[(k - ZH + 3) * PIT + row];
        }
        reinterpret_cast<float4*>(out)[(size_t)gRow * 32 + wl] = v;
    }

    // ---------------- densities: reduce 16 partials per row ----------------
    // sH is dead now; alias reduction scratch onto it.
    float* sSS = sm + OFF_SS;
    float* sLD = sm + OFF_LD;
#pragma unroll
    for (int i = 0; i < 4; i++) {
        sSS[tc * 64 + (r0 + i)] = ss_part[i];
        sLD[tc * 64 + (r0 + i)] = ld_part[i];
    }
    __syncthreads();
    if (tid < 64) {
        float ssum = 0.f, lsum = 0.f;
#pragma unroll
        for (int t = 0; t < 16; t++) {
            ssum += sSS[t * 64 + tid];
            lsum += sLD[t * 64 + tid];
        }
        int gRow = rowBase + tid;
        size_t base = (size_t)Brows * ZZ;
        out[base + gRow]         = -0.5f * ssum;
        out[base + Brows + gRow] = sQ0[tid] - lsum;
    }
}

extern "C" void kernel_launch(void* const* d_in, const int* in_sizes, int n_in,
                              void* d_out, int out_size)
{
    const float* mean   = (const float*)d_in[0];
    const float* logvar = (const float*)d_in[1];
    const float* eps    = (const float*)d_in[2];
    const float* W_in   = (const float*)d_in[3];
    const float* b_in   = (const float*)d_in[4];
    const float* W_mu   = (const float*)d_in[5];
    const float* b_mu   = (const float*)d_in[6];
    const float* W_sig  = (const float*)d_in[7];
    const float* b_sig  = (const float*)d_in[8];
    float* out = (float*)d_out;

    int Brows = in_sizes[0] / ZZ;

    static int attr_set = 0;
    if (!attr_set) {
        cudaFuncSetAttribute(flow_kernel, cudaFuncAttributeMaxDynamicSharedMemorySize, SMEM_BYTES);
        attr_set = 1;
    }

    int grid = Brows / RR;
    flow_kernel<<<grid, TPB, SMEM_BYTES>>>(mean, logvar, eps,
                                           W_in, b_in, W_mu, b_mu, W_sig, b_sig,
                                           out, Brows);
}